// round 2
// baseline (speedup 1.0000x reference)
#include <cuda_runtime.h>
#include <cstddef>

#define BATCH 2
#define SEQ   2048
#define EMBED 1024
#define HEADS 16
#define HD    64

// Scratch: qkv in [part][b][h][s][d] (part: 0=q(pre-scaled),1=k,2=v), attn out in [b][s][e]
__device__ float g_qkv[(size_t)3 * BATCH * HEADS * SEQ * HD];
__device__ float g_attn[(size_t)BATCH * SEQ * EMBED];

// ---------------------------------------------------------------------------
// Classic 128x128x8 SGEMM, 256 threads, 8x8 per thread.
// MODE 0: C[m*N+n] = acc + bias[n]
// MODE 1: QKV epilogue: scatter into g_qkv, scale Q by 1/sqrt(HD)
// ---------------------------------------------------------------------------
template <int MODE>
__global__ __launch_bounds__(256)
void sgemm_kernel(const float* __restrict__ A, const float* __restrict__ B,
                  const float* __restrict__ bias, float* __restrict__ C,
                  int M, int N, int K)
{
    __shared__ float As[8][128];
    __shared__ float Bs[8][128];

    const int tid = threadIdx.x;
    const int tx = tid & 15;   // 0..15 (col group)
    const int ty = tid >> 4;   // 0..15 (row group)
    const int row0 = blockIdx.y * 128;
    const int col0 = blockIdx.x * 128;

    // A load: 128 rows x 8 cols, one float4 per thread
    const int a_row = tid >> 1;
    const int a_col = (tid & 1) * 4;
    // B load: 8 rows x 128 cols, one float4 per thread
    const int b_row = tid >> 5;
    const int b_col = (tid & 31) * 4;

    const float* Aptr = A + (size_t)(row0 + a_row) * K + a_col;
    const float* Bptr = B + (size_t)b_row * N + col0 + b_col;

    float acc[8][8];
#pragma unroll
    for (int i = 0; i < 8; ++i)
#pragma unroll
        for (int j = 0; j < 8; ++j) acc[i][j] = 0.f;

    for (int k0 = 0; k0 < K; k0 += 8) {
        float4 av = *(const float4*)(Aptr + k0);
        float4 bv = *(const float4*)(Bptr + (size_t)k0 * N);
        As[a_col + 0][a_row] = av.x;
        As[a_col + 1][a_row] = av.y;
        As[a_col + 2][a_row] = av.z;
        As[a_col + 3][a_row] = av.w;
        *(float4*)&Bs[b_row][b_col] = bv;
        __syncthreads();

        float regM[8], regN[8];
#pragma unroll
        for (int k = 0; k < 8; ++k) {
#pragma unroll
            for (int i = 0; i < 8; ++i) regM[i] = As[k][ty * 8 + i];
#pragma unroll
            for (int j = 0; j < 8; ++j) regN[j] = Bs[k][tx * 8 + j];
#pragma unroll
            for (int i = 0; i < 8; ++i)
#pragma unroll
                for (int j = 0; j < 8; ++j)
                    acc[i][j] += regM[i] * regN[j];
        }
        __syncthreads();
    }

#pragma unroll
    for (int i = 0; i < 8; ++i) {
        const int m = row0 + ty * 8 + i;
#pragma unroll
        for (int j = 0; j < 8; ++j) {
            const int n = col0 + tx * 8 + j;
            float v = acc[i][j] + bias[n];
            if (MODE == 0) {
                C[(size_t)m * N + n] = v;
            } else {
                const int part = n >> 10;       // n / 1024
                const int e = n & 1023;
                const int h = e >> 6;
                const int d = e & 63;
                const int b = m >> 11;          // m / 2048
                const int s = m & 2047;
                if (part == 0) v *= 0.125f;     // 1/sqrt(64)
                g_qkv[((((size_t)part * BATCH + b) * HEADS + h) * SEQ + s) * HD + d] = v;
            }
        }
    }
}

// ---------------------------------------------------------------------------
// Flash attention (causal), fp32. Block: 256 threads, 64 q-rows per block.
// Key tiles of 64. Online softmax with m/l/alpha in shared memory.
// Dynamic smem: Qs/Ks/Vs/Ss each [64][65] floats = 66560 B.
// ---------------------------------------------------------------------------
__global__ __launch_bounds__(256)
void attn_kernel()
{
    extern __shared__ float sm[];
    float* Qs = sm;                 // [64][65]
    float* Ks = sm + 64 * 65;
    float* Vs = sm + 2 * 64 * 65;
    float* Ss = sm + 3 * 64 * 65;
    __shared__ float m_s[64], l_s[64], alpha_s[64];

    const int qb = blockIdx.x;      // q tile index 0..31
    const int h  = blockIdx.y;
    const int b  = blockIdx.z;
    const int tid = threadIdx.x;
    const int tx = tid & 15;        // col group 0..15
    const int ty = tid >> 4;        // row group 0..15
    const int i0 = qb * 64;

    const float* Qp = g_qkv + (((size_t)0 * BATCH + b) * HEADS + h) * SEQ * HD;
    const float* Kp = g_qkv + (((size_t)1 * BATCH + b) * HEADS + h) * SEQ * HD;
    const float* Vp = g_qkv + (((size_t)2 * BATCH + b) * HEADS + h) * SEQ * HD;

    // Load Q tile (64 rows x 64 cols), float4-granular
    for (int f = tid; f < 64 * 16; f += 256) {
        const int r = f >> 4;
        const int c4 = (f & 15) << 2;
        float4 v = *(const float4*)(Qp + (size_t)(i0 + r) * HD + c4);
        Qs[r * 65 + c4 + 0] = v.x;
        Qs[r * 65 + c4 + 1] = v.y;
        Qs[r * 65 + c4 + 2] = v.z;
        Qs[r * 65 + c4 + 3] = v.w;
    }
    if (tid < 64) { m_s[tid] = -1e30f; l_s[tid] = 0.f; }

    float acc[4][4];
#pragma unroll
    for (int i = 0; i < 4; ++i)
#pragma unroll
        for (int j = 0; j < 4; ++j) acc[i][j] = 0.f;

    const int ntiles = qb + 1;
    for (int jt = 0; jt < ntiles; ++jt) {
        const int j0 = jt * 64;
        __syncthreads();  // protect Ks/Vs/Ss reuse; covers Q-load on iter 0

        // Load K and V tiles
        for (int f = tid; f < 64 * 16; f += 256) {
            const int r = f >> 4;
            const int c4 = (f & 15) << 2;
            float4 kv = *(const float4*)(Kp + (size_t)(j0 + r) * HD + c4);
            Ks[r * 65 + c4 + 0] = kv.x;
            Ks[r * 65 + c4 + 1] = kv.y;
            Ks[r * 65 + c4 + 2] = kv.z;
            Ks[r * 65 + c4 + 3] = kv.w;
            float4 vv = *(const float4*)(Vp + (size_t)(j0 + r) * HD + c4);
            Vs[r * 65 + c4 + 0] = vv.x;
            Vs[r * 65 + c4 + 1] = vv.y;
            Vs[r * 65 + c4 + 2] = vv.z;
            Vs[r * 65 + c4 + 3] = vv.w;
        }
        __syncthreads();

        // S = Q * K^T for this tile (4x4 per thread)
        float s[4][4];
#pragma unroll
        for (int i = 0; i < 4; ++i)
#pragma unroll
            for (int j = 0; j < 4; ++j) s[i][j] = 0.f;

#pragma unroll 8
        for (int d = 0; d < 64; ++d) {
            float qreg[4], kreg[4];
#pragma unroll
            for (int i = 0; i < 4; ++i) qreg[i] = Qs[(4 * ty + i) * 65 + d];
#pragma unroll
            for (int j = 0; j < 4; ++j) kreg[j] = Ks[(4 * tx + j) * 65 + d];
#pragma unroll
            for (int i = 0; i < 4; ++i)
#pragma unroll
                for (int j = 0; j < 4; ++j)
                    s[i][j] += qreg[i] * kreg[j];
        }

        const bool diag = (jt == qb);
#pragma unroll
        for (int i = 0; i < 4; ++i) {
#pragma unroll
            for (int j = 0; j < 4; ++j) {
                const int qi = 4 * ty + i;
                const int kj = 4 * tx + j;
                float val = s[i][j];
                if (diag && (j0 + kj > i0 + qi)) val = -1e30f;
                Ss[qi * 65 + kj] = val;
            }
        }
        __syncthreads();

        // Online softmax row update (one thread per row)
        if (tid < 64) {
            const int r = tid;
            const float mold = m_s[r];
            float tmax = -1e30f;
#pragma unroll 8
            for (int j = 0; j < 64; ++j) tmax = fmaxf(tmax, Ss[r * 65 + j]);
            const float mnew = fmaxf(mold, tmax);
            const float alpha = __expf(mold - mnew);
            float rsum = 0.f;
#pragma unroll 8
            for (int j = 0; j < 64; ++j) {
                const float p = __expf(Ss[r * 65 + j] - mnew);
                Ss[r * 65 + j] = p;
                rsum += p;
            }
            l_s[r] = l_s[r] * alpha + rsum;
            m_s[r] = mnew;
            alpha_s[r] = alpha;
        }
        __syncthreads();

        // Rescale accumulator, then acc += P * V
        float al[4];
#pragma unroll
        for (int i = 0; i < 4; ++i) al[i] = alpha_s[4 * ty + i];
#pragma unroll
        for (int i = 0; i < 4; ++i)
#pragma unroll
            for (int j = 0; j < 4; ++j) acc[i][j] *= al[i];

#pragma unroll 8
        for (int k = 0; k < 64; ++k) {
            float pr[4], vr[4];
#pragma unroll
            for (int i = 0; i < 4; ++i) pr[i] = Ss[(4 * ty + i) * 65 + k];
#pragma unroll
            for (int j = 0; j < 4; ++j) vr[j] = Vs[k * 65 + 4 * tx + j];
#pragma unroll
            for (int i = 0; i < 4; ++i)
#pragma unroll
                for (int j = 0; j < 4; ++j)
                    acc[i][j] += pr[i] * vr[j];
        }
    }

    // Normalize and write to g_attn in [B, S, E] layout (E = h*64 + d)
    float inv[4];
#pragma unroll
    for (int i = 0; i < 4; ++i) inv[i] = 1.0f / l_s[4 * ty + i];
#pragma unroll
    for (int i = 0; i < 4; ++i) {
        const int srow = i0 + 4 * ty + i;
#pragma unroll
        for (int j = 0; j < 4; ++j) {
            const int d = 4 * tx + j;
            g_attn[((size_t)b * SEQ + srow) * EMBED + h * HD + d] = acc[i][j] * inv[i];
        }
    }
}

// ---------------------------------------------------------------------------
extern "C" void kernel_launch(void* const* d_in, const int* in_sizes, int n_in,
                              void* d_out, int out_size)
{
    const float* x    = (const float*)d_in[0];
    const float* Wqkv = (const float*)d_in[1];
    const float* bqkv = (const float*)d_in[2];
    const float* Wout = (const float*)d_in[3];
    const float* bout = (const float*)d_in[4];
    float* out = (float*)d_out;

    void* attn_ptr = nullptr;
    cudaGetSymbolAddress(&attn_ptr, g_attn);

    const int M = BATCH * SEQ;  // 4096

    // 1) QKV projection + bias + Q scaling + scatter to [3][B][H][S][D]
    {
        dim3 grid(3 * EMBED / 128, M / 128);  // (24, 32)
        sgemm_kernel<1><<<grid, 256>>>(x, Wqkv, bqkv, nullptr, M, 3 * EMBED, EMBED);
    }

    // 2) Causal flash attention
    {
        const size_t smem = (size_t)4 * 64 * 65 * sizeof(float);  // 66560 B
        cudaFuncSetAttribute(attn_kernel, cudaFuncAttributeMaxDynamicSharedMemorySize,
                             (int)smem);
        attn_kernel<<<dim3(SEQ / 64, HEADS, BATCH), 256, smem>>>();
    }

    // 3) Output projection straight into d_out ([B,S,E] row-major)
    {
        dim3 grid(EMBED / 128, M / 128);  // (8, 32)
        sgemm_kernel<0><<<grid, 256>>>((const float*)attn_ptr, Wout, bout, out,
                                       M, EMBED, EMBED);
    }
}

// round 4
// speedup vs baseline: 6.4431x; 6.4431x over previous
#include <cuda_runtime.h>
#include <cuda_fp16.h>
#include <cstdint>
#include <cstddef>

#define BATCH 2
#define SEQ   2048
#define EMBED 1024
#define HEADS 16
#define HD    64

// fp16 scratch: qkv [part][b][h][s][d] (q pre-scaled by 0.125*log2e), attn out [b][s][e]
__device__ __half g_qkv_h[(size_t)3 * BATCH * HEADS * SEQ * HD];
__device__ __half g_attn_h[(size_t)BATCH * SEQ * EMBED];

#define QSCALE 0.18033688f   // (1/sqrt(64)) * log2(e)

// ---------------------------------------------------------------------------
// mma.sync / ldmatrix helpers (base sm_103 ISA — no tcgen05)
// ---------------------------------------------------------------------------
__device__ __forceinline__ uint32_t smem_u32(const void* p) {
    uint32_t a;
    asm("{ .reg .u64 t; cvta.to.shared.u64 t, %1; cvt.u32.u64 %0, t; }" : "=r"(a) : "l"(p));
    return a;
}
__device__ __forceinline__ void ldm_x4(uint32_t* r, uint32_t addr) {
    asm volatile("ldmatrix.sync.aligned.m8n8.x4.shared.b16 {%0,%1,%2,%3}, [%4];"
                 : "=r"(r[0]), "=r"(r[1]), "=r"(r[2]), "=r"(r[3]) : "r"(addr));
}
__device__ __forceinline__ void ldm_x4_t(uint32_t* r, uint32_t addr) {
    asm volatile("ldmatrix.sync.aligned.m8n8.x4.trans.shared.b16 {%0,%1,%2,%3}, [%4];"
                 : "=r"(r[0]), "=r"(r[1]), "=r"(r[2]), "=r"(r[3]) : "r"(addr));
}
__device__ __forceinline__ void mma16816(float* d, const uint32_t* a, const uint32_t* b) {
    asm volatile(
        "mma.sync.aligned.m16n8k16.row.col.f32.f16.f16.f32 "
        "{%0,%1,%2,%3}, {%4,%5,%6,%7}, {%8,%9}, {%0,%1,%2,%3};"
        : "+f"(d[0]), "+f"(d[1]), "+f"(d[2]), "+f"(d[3])
        : "r"(a[0]), "r"(a[1]), "r"(a[2]), "r"(a[3]), "r"(b[0]), "r"(b[1]));
}
__device__ __forceinline__ uint32_t packh2(float x, float y) {
    __half2 h = __floats2half2_rn(x, y);
    return *reinterpret_cast<uint32_t*>(&h);
}

// ---------------------------------------------------------------------------
// fp16 HMMA GEMM: C[M,N] = A[M,K] @ B[K,N] + bias
// CTA 128x128, BK=32, 256 threads (8 warps: 4m x 2n), warp tile 32x64.
// AT = float (convert) or __half (direct). MODE 0: C fp32. MODE 1: QKV scatter.
// ---------------------------------------------------------------------------
#define BM 128
#define BN 128
#define BK 32
#define APAD 8
#define BPAD 8

template <int MODE, typename AT>
__global__ __launch_bounds__(256)
void hgemm(const AT* __restrict__ A, const float* __restrict__ B,
           const float* __restrict__ bias, float* __restrict__ C,
           int M, int N, int K)
{
    __shared__ __half As[2][BM][BK + APAD];
    __shared__ __half Bs[2][BK][BN + BPAD];

    const int tid = threadIdx.x;
    const int lane = tid & 31;
    const int wid = tid >> 5;
    const int wy = wid >> 1;   // 0..3
    const int wx = wid & 1;    // 0..1
    const int row0 = blockIdx.y * BM;
    const int col0 = blockIdx.x * BN;

    float acc[2][8][4];
#pragma unroll
    for (int i = 0; i < 2; ++i)
#pragma unroll
        for (int j = 0; j < 8; ++j)
#pragma unroll
            for (int v = 0; v < 4; ++v) acc[i][j][v] = 0.f;

    const int nch = K / BK;

    // prefetch registers
    float4 pa[4];  uint4 pah[2];  float4 pb[4];

    auto prefetch = [&](int c) {
        if (sizeof(AT) == 4) {
#pragma unroll
            for (int it = 0; it < 4; ++it) {
                const int g = tid + it * 256;
                const int r = g >> 3, q = g & 7;
                pa[it] = *(const float4*)((const float*)A + (size_t)(row0 + r) * K + c * BK + q * 4);
            }
        } else {
#pragma unroll
            for (int it = 0; it < 2; ++it) {
                const int g = tid + it * 256;
                const int r = g >> 2, q = g & 3;
                pah[it] = *(const uint4*)((const __half*)A + (size_t)(row0 + r) * K + c * BK + q * 8);
            }
        }
#pragma unroll
        for (int it = 0; it < 4; ++it) {
            const int g = tid + it * 256;
            const int r = g >> 5, n = (g & 31) * 4;
            pb[it] = *(const float4*)(B + (size_t)(c * BK + r) * N + col0 + n);
        }
    };
    auto stage = [&](int buf) {
        if (sizeof(AT) == 4) {
#pragma unroll
            for (int it = 0; it < 4; ++it) {
                const int g = tid + it * 256;
                const int r = g >> 3, q = g & 7;
                uint2 w = {packh2(pa[it].x, pa[it].y), packh2(pa[it].z, pa[it].w)};
                *(uint2*)&As[buf][r][q * 4] = w;
            }
        } else {
#pragma unroll
            for (int it = 0; it < 2; ++it) {
                const int g = tid + it * 256;
                const int r = g >> 2, q = g & 3;
                *(uint4*)&As[buf][r][q * 8] = pah[it];
            }
        }
#pragma unroll
        for (int it = 0; it < 4; ++it) {
            const int g = tid + it * 256;
            const int r = g >> 5, n = (g & 31) * 4;
            uint2 w = {packh2(pb[it].x, pb[it].y), packh2(pb[it].z, pb[it].w)};
            *(uint2*)&Bs[buf][r][n] = w;
        }
    };

    prefetch(0);
    stage(0);
    __syncthreads();

    for (int c = 0; c < nch; ++c) {
        const int p = c & 1;
        if (c + 1 < nch) prefetch(c + 1);

#pragma unroll
        for (int kk = 0; kk < 2; ++kk) {
            uint32_t af[2][4];
#pragma unroll
            for (int i = 0; i < 2; ++i)
                ldm_x4(af[i], smem_u32(&As[p][wy * 32 + i * 16 + (lane & 15)][kk * 16 + (lane >> 4) * 8]));
            uint32_t bf[4][4];
#pragma unroll
            for (int q = 0; q < 4; ++q)
                ldm_x4_t(bf[q], smem_u32(&Bs[p][kk * 16 + (lane & 15)][wx * 64 + q * 16 + (lane >> 4) * 8]));
#pragma unroll
            for (int i = 0; i < 2; ++i)
#pragma unroll
                for (int q = 0; q < 4; ++q) {
                    mma16816(acc[i][2 * q + 0], af[i], &bf[q][0]);
                    mma16816(acc[i][2 * q + 1], af[i], &bf[q][2]);
                }
        }

        if (c + 1 < nch) stage(1 - p);
        __syncthreads();
    }

    // epilogue straight from C fragments
#pragma unroll
    for (int i = 0; i < 2; ++i) {
        const int ra = row0 + wy * 32 + i * 16 + (lane >> 2);
#pragma unroll
        for (int j = 0; j < 8; ++j) {
            const int n = col0 + wx * 64 + j * 8 + (lane & 3) * 2;
            const float b0 = bias[n], b1 = bias[n + 1];
#pragma unroll
            for (int half = 0; half < 2; ++half) {
                const int m = ra + half * 8;
                float v0 = acc[i][j][2 * half + 0] + b0;
                float v1 = acc[i][j][2 * half + 1] + b1;
                if (MODE == 0) {
                    *(float2*)&C[(size_t)m * N + n] = make_float2(v0, v1);
                } else {
                    const int part = n >> 10;
                    const int e = n & 1023;
                    const int h = e >> 6;
                    const int d = e & 63;
                    const int bb = m >> 11;
                    const int s = m & 2047;
                    if (part == 0) { v0 *= QSCALE; v1 *= QSCALE; }
                    __half2 hv = __floats2half2_rn(v0, v1);
                    *(__half2*)&g_qkv_h[((((size_t)part * BATCH + bb) * HEADS + h) * SEQ + s) * HD + d] = hv;
                }
            }
        }
    }
}

// ---------------------------------------------------------------------------
// FlashAttention-2 with fp16 mma.sync. Block = 128 threads (4 warps),
// each warp owns 16 q-rows; q-tile 64, kv-tile 64. exp2-domain softmax
// (Q pre-scaled by 0.125*log2e at the QKV epilogue).
// ---------------------------------------------------------------------------
__global__ __launch_bounds__(128)
void fattn()
{
    __shared__ __half Qs[64][72];
    __shared__ __half Ks[64][72];
    __shared__ __half Vs[64][72];

    const int qb = blockIdx.x;
    const int h  = blockIdx.y;
    const int b  = blockIdx.z;
    const int tid = threadIdx.x;
    const int lane = tid & 31;
    const int w = tid >> 5;
    const int i0 = qb * 64;

    const __half* Qp = g_qkv_h + (((size_t)0 * BATCH + b) * HEADS + h) * SEQ * HD;
    const __half* Kp = g_qkv_h + (((size_t)1 * BATCH + b) * HEADS + h) * SEQ * HD;
    const __half* Vp = g_qkv_h + (((size_t)2 * BATCH + b) * HEADS + h) * SEQ * HD;

    // load Q tile, extract per-warp fragments
#pragma unroll
    for (int it = 0; it < 4; ++it) {
        const int g = tid + it * 128;
        const int r = g >> 3, q = g & 7;
        *(uint4*)&Qs[r][q * 8] = *(const uint4*)(Qp + (size_t)(i0 + r) * HD + q * 8);
    }
    __syncthreads();
    uint32_t qf[4][4];
#pragma unroll
    for (int kk = 0; kk < 4; ++kk)
        ldm_x4(qf[kk], smem_u32(&Qs[w * 16 + (lane & 15)][kk * 16 + (lane >> 4) * 8]));
    __syncthreads();

    float o[8][4];
#pragma unroll
    for (int j = 0; j < 8; ++j)
#pragma unroll
        for (int v = 0; v < 4; ++v) o[j][v] = 0.f;
    float m_a = -1e30f, m_b = -1e30f, l_a = 0.f, l_b = 0.f;

    const int rowa = i0 + w * 16 + (lane >> 2);
    const int rowb = rowa + 8;

    for (int jt = 0; jt <= qb; ++jt) {
        const int j0 = jt * 64;
        // load K,V tiles
#pragma unroll
        for (int it = 0; it < 4; ++it) {
            const int g = tid + it * 128;
            const int r = g >> 3, q = g & 7;
            *(uint4*)&Ks[r][q * 8] = *(const uint4*)(Kp + (size_t)(j0 + r) * HD + q * 8);
            *(uint4*)&Vs[r][q * 8] = *(const uint4*)(Vp + (size_t)(j0 + r) * HD + q * 8);
        }
        __syncthreads();

        // S = Q @ K^T  (8 n8-tiles per warp)
        float s[8][4];
#pragma unroll
        for (int j = 0; j < 8; ++j)
#pragma unroll
            for (int v = 0; v < 4; ++v) s[j][v] = 0.f;
#pragma unroll
        for (int kk = 0; kk < 4; ++kk) {
            uint32_t kf[4][4];
#pragma unroll
            for (int np = 0; np < 4; ++np) {
                const int r8 = lane & 7, sel = lane >> 3;
                const int n = np * 16 + (sel >> 1) * 8 + r8;
                const int k = kk * 16 + (sel & 1) * 8;
                ldm_x4(kf[np], smem_u32(&Ks[n][k]));
            }
#pragma unroll
            for (int np = 0; np < 4; ++np) {
                mma16816(s[2 * np + 0], qf[kk], &kf[np][0]);
                mma16816(s[2 * np + 1], qf[kk], &kf[np][2]);
            }
        }

        // causal mask on diagonal tile
        if (jt == qb) {
#pragma unroll
            for (int j = 0; j < 8; ++j) {
                const int c0 = j0 + j * 8 + (lane & 3) * 2;
                if (c0 > rowa)     s[j][0] = -1e30f;
                if (c0 + 1 > rowa) s[j][1] = -1e30f;
                if (c0 > rowb)     s[j][2] = -1e30f;
                if (c0 + 1 > rowb) s[j][3] = -1e30f;
            }
        }

        // online softmax (exp2 domain)
        float ma = -1e30f, mb = -1e30f;
#pragma unroll
        for (int j = 0; j < 8; ++j) {
            ma = fmaxf(ma, fmaxf(s[j][0], s[j][1]));
            mb = fmaxf(mb, fmaxf(s[j][2], s[j][3]));
        }
        ma = fmaxf(ma, __shfl_xor_sync(0xffffffff, ma, 1));
        ma = fmaxf(ma, __shfl_xor_sync(0xffffffff, ma, 2));
        mb = fmaxf(mb, __shfl_xor_sync(0xffffffff, mb, 1));
        mb = fmaxf(mb, __shfl_xor_sync(0xffffffff, mb, 2));

        const float mna = fmaxf(m_a, ma), mnb = fmaxf(m_b, mb);
        const float alpha_a = exp2f(m_a - mna), alpha_b = exp2f(m_b - mnb);
        m_a = mna; m_b = mnb;

        float sa = 0.f, sb = 0.f;
#pragma unroll
        for (int j = 0; j < 8; ++j) {
            s[j][0] = exp2f(s[j][0] - mna);
            s[j][1] = exp2f(s[j][1] - mna);
            s[j][2] = exp2f(s[j][2] - mnb);
            s[j][3] = exp2f(s[j][3] - mnb);
            sa += s[j][0] + s[j][1];
            sb += s[j][2] + s[j][3];
        }
        sa += __shfl_xor_sync(0xffffffff, sa, 1);
        sa += __shfl_xor_sync(0xffffffff, sa, 2);
        sb += __shfl_xor_sync(0xffffffff, sb, 1);
        sb += __shfl_xor_sync(0xffffffff, sb, 2);
        l_a = l_a * alpha_a + sa;
        l_b = l_b * alpha_b + sb;

#pragma unroll
        for (int j = 0; j < 8; ++j) {
            o[j][0] *= alpha_a; o[j][1] *= alpha_a;
            o[j][2] *= alpha_b; o[j][3] *= alpha_b;
        }

        // O += P @ V
#pragma unroll
        for (int kk = 0; kk < 4; ++kk) {
            uint32_t pf[4];
            pf[0] = packh2(s[2 * kk][0],     s[2 * kk][1]);
            pf[1] = packh2(s[2 * kk][2],     s[2 * kk][3]);
            pf[2] = packh2(s[2 * kk + 1][0], s[2 * kk + 1][1]);
            pf[3] = packh2(s[2 * kk + 1][2], s[2 * kk + 1][3]);
#pragma unroll
            for (int dp = 0; dp < 4; ++dp) {
                uint32_t vf[4];
                ldm_x4_t(vf, smem_u32(&Vs[kk * 16 + (lane & 15)][dp * 16 + (lane >> 4) * 8]));
                mma16816(o[2 * dp + 0], pf, &vf[0]);
                mma16816(o[2 * dp + 1], pf, &vf[2]);
            }
        }
        __syncthreads();
    }

    // normalize + store fp16 to g_attn_h [b][s][e]
    const float inva = 1.f / l_a, invb = 1.f / l_b;
#pragma unroll
    for (int j = 0; j < 8; ++j) {
        const int e = h * HD + j * 8 + (lane & 3) * 2;
        *(__half2*)&g_attn_h[((size_t)b * SEQ + rowa) * EMBED + e] =
            __floats2half2_rn(o[j][0] * inva, o[j][1] * inva);
        *(__half2*)&g_attn_h[((size_t)b * SEQ + rowb) * EMBED + e] =
            __floats2half2_rn(o[j][2] * invb, o[j][3] * invb);
    }
}

// ---------------------------------------------------------------------------
extern "C" void kernel_launch(void* const* d_in, const int* in_sizes, int n_in,
                              void* d_out, int out_size)
{
    const float* x    = (const float*)d_in[0];
    const float* Wqkv = (const float*)d_in[1];
    const float* bqkv = (const float*)d_in[2];
    const float* Wout = (const float*)d_in[3];
    const float* bout = (const float*)d_in[4];
    float* out = (float*)d_out;

    void* attn_ptr = nullptr;
    cudaGetSymbolAddress(&attn_ptr, g_attn_h);

    const int M = BATCH * SEQ;  // 4096

    // 1) QKV projection + bias + Q prescale(0.125*log2e) + fp16 scatter
    {
        dim3 grid(3 * EMBED / BN, M / BM);  // (24, 32)
        hgemm<1, float><<<grid, 256>>>(x, Wqkv, bqkv, nullptr, M, 3 * EMBED, EMBED);
    }

    // 2) Causal flash attention (fp16 HMMA)
    fattn<<<dim3(SEQ / 64, HEADS, BATCH), 128>>>();

    // 3) Output projection (A = fp16 attn output) -> fp32 d_out
    {
        dim3 grid(EMBED / BN, M / BM);  // (8, 32)
        hgemm<0, __half><<<grid, 256>>>((const __half*)attn_ptr, Wout, bout, out,
                                        M, EMBED, EMBED);
    }
}

// round 5
// speedup vs baseline: 7.9682x; 1.2367x over previous
#include <cuda_runtime.h>
#include <cuda_fp16.h>
#include <cstdint>
#include <cstddef>

#define BATCH 2
#define SEQ   2048
#define EMBED 1024
#define HEADS 16
#define HD    64

// fp16 scratch
__device__ __half g_xh[(size_t)BATCH * SEQ * EMBED];              // x fp16
__device__ __half g_wq_h[(size_t)EMBED * 3 * EMBED];              // W_qkv fp16
__device__ __half g_wo_h[(size_t)EMBED * EMBED];                  // W_out fp16
__device__ __half g_qkv_h[(size_t)3 * BATCH * HEADS * SEQ * HD];  // q(prescaled)/k/v
__device__ __half g_attn_h[(size_t)BATCH * SEQ * EMBED];          // attn out

#define QSCALE 0.18033688f   // (1/sqrt(64)) * log2(e)

// ---------------------------------------------------------------------------
// helpers
// ---------------------------------------------------------------------------
__device__ __forceinline__ uint32_t smem_u32(const void* p) {
    uint32_t a;
    asm("{ .reg .u64 t; cvta.to.shared.u64 t, %1; cvt.u32.u64 %0, t; }" : "=r"(a) : "l"(p));
    return a;
}
__device__ __forceinline__ void ldm_x4(uint32_t* r, uint32_t addr) {
    asm volatile("ldmatrix.sync.aligned.m8n8.x4.shared.b16 {%0,%1,%2,%3}, [%4];"
                 : "=r"(r[0]), "=r"(r[1]), "=r"(r[2]), "=r"(r[3]) : "r"(addr));
}
__device__ __forceinline__ void ldm_x4_t(uint32_t* r, uint32_t addr) {
    asm volatile("ldmatrix.sync.aligned.m8n8.x4.trans.shared.b16 {%0,%1,%2,%3}, [%4];"
                 : "=r"(r[0]), "=r"(r[1]), "=r"(r[2]), "=r"(r[3]) : "r"(addr));
}
__device__ __forceinline__ void mma16816(float* d, const uint32_t* a, const uint32_t* b) {
    asm volatile(
        "mma.sync.aligned.m16n8k16.row.col.f32.f16.f16.f32 "
        "{%0,%1,%2,%3}, {%4,%5,%6,%7}, {%8,%9}, {%0,%1,%2,%3};"
        : "+f"(d[0]), "+f"(d[1]), "+f"(d[2]), "+f"(d[3])
        : "r"(a[0]), "r"(a[1]), "r"(a[2]), "r"(a[3]), "r"(b[0]), "r"(b[1]));
}
__device__ __forceinline__ uint32_t packh2(float x, float y) {
    __half2 h = __floats2half2_rn(x, y);
    return *reinterpret_cast<uint32_t*>(&h);
}
__device__ __forceinline__ float ex2(float x) {
    float r;
    asm("ex2.approx.ftz.f32 %0, %1;" : "=f"(r) : "f"(x));
    return r;
}
#define CP16(dst, src) asm volatile("cp.async.cg.shared.global [%0], [%1], 16;" :: "r"(dst), "l"(src))
#define CP_COMMIT()    asm volatile("cp.async.commit_group;" ::: "memory")
#define CP_WAIT(n)     asm volatile("cp.async.wait_group %0;" :: "n"(n) : "memory")

// ---------------------------------------------------------------------------
// fp32 -> fp16 conversion of x, W_qkv, W_out (float4 granular)
// ---------------------------------------------------------------------------
#define XF4   ((size_t)BATCH * SEQ * EMBED / 4)          // 1048576
#define WQF4  ((size_t)EMBED * 3 * EMBED / 4)            // 786432
#define WOF4  ((size_t)EMBED * EMBED / 4)                // 262144
#define TOTF4 (XF4 + WQF4 + WOF4)

__global__ __launch_bounds__(256)
void convert_kernel(const float* __restrict__ x, const float* __restrict__ wq,
                    const float* __restrict__ wo)
{
    size_t i = (size_t)blockIdx.x * 256 + threadIdx.x;
    if (i >= TOTF4) return;
    const float* src;
    __half* dst;
    size_t off;
    if (i < XF4)                { src = x;  dst = g_xh;   off = i; }
    else if (i < XF4 + WQF4)    { src = wq; dst = g_wq_h; off = i - XF4; }
    else                        { src = wo; dst = g_wo_h; off = i - XF4 - WQF4; }
    float4 v = *(const float4*)(src + off * 4);
    uint2 w = {packh2(v.x, v.y), packh2(v.z, v.w)};
    *(uint2*)(dst + off * 4) = w;
}

// ---------------------------------------------------------------------------
// pure-fp16 HMMA GEMM with cp.async 3-stage pipeline.
// CTA 128x128, BK=32, 256 threads (8 warps, 4m x 2n), warp tile 32x64.
// MODE 0: C fp32 = acc + bias.  MODE 1: QKV scatter + Q prescale, fp16 out.
// ---------------------------------------------------------------------------
#define BM 128
#define BN 128
#define BK 32
#define STAGES 3
#define AST 40    // BK + 8 pad (halves)
#define BST 136   // BN + 8 pad (halves)
#define A_STAGE (BM * AST)          // halves per A stage
#define B_STAGE (BK * BST)
#define GEMM_SMEM ((STAGES * A_STAGE + STAGES * B_STAGE) * 2)   // 56832 B

template <int MODE>
__global__ __launch_bounds__(256)
void hgemm(const __half* __restrict__ A, const __half* __restrict__ B,
           const float* __restrict__ bias, float* __restrict__ C,
           int M, int N, int K)
{
    extern __shared__ __half sm[];
    __half* As = sm;                       // [STAGES][BM][AST]
    __half* Bs = sm + STAGES * A_STAGE;    // [STAGES][BK][BST]

    const int tid = threadIdx.x;
    const int lane = tid & 31;
    const int wid = tid >> 5;
    const int wy = wid >> 1;
    const int wx = wid & 1;
    const int row0 = blockIdx.y * BM;
    const int col0 = blockIdx.x * BN;

    float acc[2][8][4];
#pragma unroll
    for (int i = 0; i < 2; ++i)
#pragma unroll
        for (int j = 0; j < 8; ++j)
#pragma unroll
            for (int v = 0; v < 4; ++v) acc[i][j][v] = 0.f;

    const int nch = K / BK;

    // A: 512 16B-chunks (r = idx>>2, c8 = (idx&3)*8), 2 per thread
    // B: 512 16B-chunks (r = idx>>4, n8 = (idx&15)*8), 2 per thread
    auto load = [&](int c, int st) {
        __half* as = As + st * A_STAGE;
        __half* bs = Bs + st * B_STAGE;
#pragma unroll
        for (int it = 0; it < 2; ++it) {
            const int idx = tid + it * 256;
            const int r = idx >> 2, c8 = (idx & 3) * 8;
            CP16(smem_u32(as + r * AST + c8),
                 A + (size_t)(row0 + r) * K + c * BK + c8);
        }
#pragma unroll
        for (int it = 0; it < 2; ++it) {
            const int idx = tid + it * 256;
            const int r = idx >> 4, n8 = (idx & 15) * 8;
            CP16(smem_u32(bs + r * BST + n8),
                 B + (size_t)(c * BK + r) * N + col0 + n8);
        }
    };

    load(0, 0); CP_COMMIT();
    load(1, 1); CP_COMMIT();
    CP_WAIT(1);
    __syncthreads();

    for (int c = 0; c < nch; ++c) {
        const int p = c % STAGES;
        const __half* as = As + p * A_STAGE;
        const __half* bs = Bs + p * B_STAGE;

#pragma unroll
        for (int kk = 0; kk < 2; ++kk) {
            uint32_t af[2][4];
#pragma unroll
            for (int i = 0; i < 2; ++i)
                ldm_x4(af[i], smem_u32(as + (wy * 32 + i * 16 + (lane & 15)) * AST
                                          + kk * 16 + (lane >> 4) * 8));
            uint32_t bf[4][4];
#pragma unroll
            for (int q = 0; q < 4; ++q)
                ldm_x4_t(bf[q], smem_u32(bs + (kk * 16 + (lane & 15)) * BST
                                            + wx * 64 + q * 16 + (lane >> 4) * 8));
#pragma unroll
            for (int i = 0; i < 2; ++i)
#pragma unroll
                for (int q = 0; q < 4; ++q) {
                    mma16816(acc[i][2 * q + 0], af[i], &bf[q][0]);
                    mma16816(acc[i][2 * q + 1], af[i], &bf[q][2]);
                }
        }

        if (c + 2 < nch) {
            load(c + 2, (c + 2) % STAGES);
            CP_COMMIT();
            CP_WAIT(1);
            __syncthreads();
        } else if (c + 1 < nch) {
            CP_WAIT(0);
            __syncthreads();
        }
    }

    // epilogue from C fragments
#pragma unroll
    for (int i = 0; i < 2; ++i) {
        const int ra = row0 + wy * 32 + i * 16 + (lane >> 2);
#pragma unroll
        for (int j = 0; j < 8; ++j) {
            const int n = col0 + wx * 64 + j * 8 + (lane & 3) * 2;
            const float b0 = bias[n], b1 = bias[n + 1];
#pragma unroll
            for (int half = 0; half < 2; ++half) {
                const int m = ra + half * 8;
                float v0 = acc[i][j][2 * half + 0] + b0;
                float v1 = acc[i][j][2 * half + 1] + b1;
                if (MODE == 0) {
                    *(float2*)&C[(size_t)m * N + n] = make_float2(v0, v1);
                } else {
                    const int part = n >> 10;
                    const int e = n & 1023;
                    const int h = e >> 6;
                    const int d = e & 63;
                    const int bb = m >> 11;
                    const int s = m & 2047;
                    if (part == 0) { v0 *= QSCALE; v1 *= QSCALE; }
                    __half2 hv = __floats2half2_rn(v0, v1);
                    *(__half2*)&g_qkv_h[((((size_t)part * BATCH + bb) * HEADS + h) * SEQ + s) * HD + d] = hv;
                }
            }
        }
    }
}

// ---------------------------------------------------------------------------
// FlashAttention-2, fp16 mma.sync, cp.async double-buffered K/V tiles.
// 128 threads (4 warps x 16 q-rows), q-tile 64, kv-tile 64, exp2 softmax.
// ---------------------------------------------------------------------------
__global__ __launch_bounds__(128)
void fattn()
{
    __shared__ __half Qs[64][72];
    __shared__ __half Ks[2][64][72];
    __shared__ __half Vs[2][64][72];

    const int qb = blockIdx.x;
    const int h  = blockIdx.y;
    const int b  = blockIdx.z;
    const int tid = threadIdx.x;
    const int lane = tid & 31;
    const int w = tid >> 5;
    const int i0 = qb * 64;

    const __half* Qp = g_qkv_h + (((size_t)0 * BATCH + b) * HEADS + h) * SEQ * HD;
    const __half* Kp = g_qkv_h + (((size_t)1 * BATCH + b) * HEADS + h) * SEQ * HD;
    const __half* Vp = g_qkv_h + (((size_t)2 * BATCH + b) * HEADS + h) * SEQ * HD;

    auto loadKV = [&](int jt, int buf) {
        const int j0 = jt * 64;
#pragma unroll
        for (int it = 0; it < 4; ++it) {
            const int idx = tid + it * 128;
            const int r = idx >> 3, c8 = (idx & 7) * 8;
            CP16(smem_u32(&Ks[buf][r][c8]), Kp + (size_t)(j0 + r) * HD + c8);
            CP16(smem_u32(&Vs[buf][r][c8]), Vp + (size_t)(j0 + r) * HD + c8);
        }
    };

    // Q tile -> smem -> per-warp fragments
#pragma unroll
    for (int it = 0; it < 4; ++it) {
        const int g = tid + it * 128;
        const int r = g >> 3, q = g & 7;
        *(uint4*)&Qs[r][q * 8] = *(const uint4*)(Qp + (size_t)(i0 + r) * HD + q * 8);
    }
    loadKV(0, 0); CP_COMMIT();
    __syncthreads();
    uint32_t qf[4][4];
#pragma unroll
    for (int kk = 0; kk < 4; ++kk)
        ldm_x4(qf[kk], smem_u32(&Qs[w * 16 + (lane & 15)][kk * 16 + (lane >> 4) * 8]));

    float o[8][4];
#pragma unroll
    for (int j = 0; j < 8; ++j)
#pragma unroll
        for (int v = 0; v < 4; ++v) o[j][v] = 0.f;
    float m_a = -1e30f, m_b = -1e30f, l_a = 0.f, l_b = 0.f;

    const int rowa = i0 + w * 16 + (lane >> 2);
    const int rowb = rowa + 8;

    for (int jt = 0; jt <= qb; ++jt) {
        const int j0 = jt * 64;
        const int buf = jt & 1;
        if (jt < qb) {
            loadKV(jt + 1, buf ^ 1);
            CP_COMMIT();
            CP_WAIT(1);
        } else {
            CP_WAIT(0);
        }
        __syncthreads();

        // S = Q @ K^T
        float s[8][4];
#pragma unroll
        for (int j = 0; j < 8; ++j)
#pragma unroll
            for (int v = 0; v < 4; ++v) s[j][v] = 0.f;
#pragma unroll
        for (int kk = 0; kk < 4; ++kk) {
            uint32_t kf[4][4];
#pragma unroll
            for (int np = 0; np < 4; ++np) {
                const int r8 = lane & 7, sel = lane >> 3;
                const int n = np * 16 + (sel >> 1) * 8 + r8;
                const int k = kk * 16 + (sel & 1) * 8;
                ldm_x4(kf[np], smem_u32(&Ks[buf][n][k]));
            }
#pragma unroll
            for (int np = 0; np < 4; ++np) {
                mma16816(s[2 * np + 0], qf[kk], &kf[np][0]);
                mma16816(s[2 * np + 1], qf[kk], &kf[np][2]);
            }
        }

        if (jt == qb) {
#pragma unroll
            for (int j = 0; j < 8; ++j) {
                const int c0 = j0 + j * 8 + (lane & 3) * 2;
                if (c0 > rowa)     s[j][0] = -1e30f;
                if (c0 + 1 > rowa) s[j][1] = -1e30f;
                if (c0 > rowb)     s[j][2] = -1e30f;
                if (c0 + 1 > rowb) s[j][3] = -1e30f;
            }
        }

        float ma = -1e30f, mb = -1e30f;
#pragma unroll
        for (int j = 0; j < 8; ++j) {
            ma = fmaxf(ma, fmaxf(s[j][0], s[j][1]));
            mb = fmaxf(mb, fmaxf(s[j][2], s[j][3]));
        }
        ma = fmaxf(ma, __shfl_xor_sync(0xffffffff, ma, 1));
        ma = fmaxf(ma, __shfl_xor_sync(0xffffffff, ma, 2));
        mb = fmaxf(mb, __shfl_xor_sync(0xffffffff, mb, 1));
        mb = fmaxf(mb, __shfl_xor_sync(0xffffffff, mb, 2));

        const float mna = fmaxf(m_a, ma), mnb = fmaxf(m_b, mb);
        const float alpha_a = ex2(m_a - mna), alpha_b = ex2(m_b - mnb);
        m_a = mna; m_b = mnb;

        float sa = 0.f, sb = 0.f;
#pragma unroll
        for (int j = 0; j < 8; ++j) {
            s[j][0] = ex2(s[j][0] - mna);
            s[j][1] = ex2(s[j][1] - mna);
            s[j][2] = ex2(s[j][2] - mnb);
            s[j][3] = ex2(s[j][3] - mnb);
            sa += s[j][0] + s[j][1];
            sb += s[j][2] + s[j][3];
        }
        sa += __shfl_xor_sync(0xffffffff, sa, 1);
        sa += __shfl_xor_sync(0xffffffff, sa, 2);
        sb += __shfl_xor_sync(0xffffffff, sb, 1);
        sb += __shfl_xor_sync(0xffffffff, sb, 2);
        l_a = l_a * alpha_a + sa;
        l_b = l_b * alpha_b + sb;

#pragma unroll
        for (int j = 0; j < 8; ++j) {
            o[j][0] *= alpha_a; o[j][1] *= alpha_a;
            o[j][2] *= alpha_b; o[j][3] *= alpha_b;
        }

        // O += P @ V
#pragma unroll
        for (int kk = 0; kk < 4; ++kk) {
            uint32_t pf[4];
            pf[0] = packh2(s[2 * kk][0],     s[2 * kk][1]);
            pf[1] = packh2(s[2 * kk][2],     s[2 * kk][3]);
            pf[2] = packh2(s[2 * kk + 1][0], s[2 * kk + 1][1]);
            pf[3] = packh2(s[2 * kk + 1][2], s[2 * kk + 1][3]);
#pragma unroll
            for (int dp = 0; dp < 4; ++dp) {
                uint32_t vf[4];
                ldm_x4_t(vf, smem_u32(&Vs[buf][kk * 16 + (lane & 15)][dp * 16 + (lane >> 4) * 8]));
                mma16816(o[2 * dp + 0], pf, &vf[0]);
                mma16816(o[2 * dp + 1], pf, &vf[2]);
            }
        }
        __syncthreads();
    }

    const float inva = 1.f / l_a, invb = 1.f / l_b;
#pragma unroll
    for (int j = 0; j < 8; ++j) {
        const int e = h * HD + j * 8 + (lane & 3) * 2;
        *(__half2*)&g_attn_h[((size_t)b * SEQ + rowa) * EMBED + e] =
            __floats2half2_rn(o[j][0] * inva, o[j][1] * inva);
        *(__half2*)&g_attn_h[((size_t)b * SEQ + rowb) * EMBED + e] =
            __floats2half2_rn(o[j][2] * invb, o[j][3] * invb);
    }
}

// ---------------------------------------------------------------------------
extern "C" void kernel_launch(void* const* d_in, const int* in_sizes, int n_in,
                              void* d_out, int out_size)
{
    const float* x    = (const float*)d_in[0];
    const float* Wqkv = (const float*)d_in[1];
    const float* bqkv = (const float*)d_in[2];
    const float* Wout = (const float*)d_in[3];
    const float* bout = (const float*)d_in[4];
    float* out = (float*)d_out;

    void *xh_p = nullptr, *wq_p = nullptr, *wo_p = nullptr, *attn_p = nullptr;
    cudaGetSymbolAddress(&xh_p, g_xh);
    cudaGetSymbolAddress(&wq_p, g_wq_h);
    cudaGetSymbolAddress(&wo_p, g_wo_h);
    cudaGetSymbolAddress(&attn_p, g_attn_h);

    const int M = BATCH * SEQ;  // 4096

    cudaFuncSetAttribute(hgemm<0>, cudaFuncAttributeMaxDynamicSharedMemorySize, GEMM_SMEM);
    cudaFuncSetAttribute(hgemm<1>, cudaFuncAttributeMaxDynamicSharedMemorySize, GEMM_SMEM);

    // 0) fp32 -> fp16 conversion of x, W_qkv, W_out
    convert_kernel<<<(unsigned)((TOTF4 + 255) / 256), 256>>>(x, Wqkv, Wout);

    // 1) QKV projection + bias + Q prescale + fp16 scatter
    {
        dim3 grid(3 * EMBED / BN, M / BM);  // (24, 32)
        hgemm<1><<<grid, 256, GEMM_SMEM>>>((const __half*)xh_p, (const __half*)wq_p,
                                           bqkv, nullptr, M, 3 * EMBED, EMBED);
    }

    // 2) Causal flash attention
    fattn<<<dim3(SEQ / 64, HEADS, BATCH), 128>>>();

    // 3) Output projection -> fp32 d_out
    {
        dim3 grid(EMBED / BN, M / BM);  // (8, 32)
        hgemm<0><<<grid, 256, GEMM_SMEM>>>((const __half*)attn_p, (const __half*)wo_p,
                                           bout, out, M, EMBED, EMBED);
    }
}

// round 6
// speedup vs baseline: 8.3537x; 1.0484x over previous
#include <cuda_runtime.h>
#include <cuda_fp16.h>
#include <cstdint>
#include <cstddef>

#define BATCH 2
#define SEQ   2048
#define EMBED 1024
#define HEADS 16
#define HD    64

__device__ __half g_xh[(size_t)BATCH * SEQ * EMBED];
__device__ __half g_wq_h[(size_t)EMBED * 3 * EMBED];
__device__ __half g_wo_h[(size_t)EMBED * EMBED];
__device__ __half g_qkv_h[(size_t)3 * BATCH * HEADS * SEQ * HD];
__device__ __half g_attn_h[(size_t)BATCH * SEQ * EMBED];

#define QSCALE 0.18033688f   // (1/sqrt(64)) * log2(e)

// ---------------------------------------------------------------------------
__device__ __forceinline__ uint32_t smem_u32(const void* p) {
    uint32_t a;
    asm("{ .reg .u64 t; cvta.to.shared.u64 t, %1; cvt.u32.u64 %0, t; }" : "=r"(a) : "l"(p));
    return a;
}
__device__ __forceinline__ void ldm_x4(uint32_t* r, uint32_t addr) {
    asm volatile("ldmatrix.sync.aligned.m8n8.x4.shared.b16 {%0,%1,%2,%3}, [%4];"
                 : "=r"(r[0]), "=r"(r[1]), "=r"(r[2]), "=r"(r[3]) : "r"(addr));
}
__device__ __forceinline__ void ldm_x4_t(uint32_t* r, uint32_t addr) {
    asm volatile("ldmatrix.sync.aligned.m8n8.x4.trans.shared.b16 {%0,%1,%2,%3}, [%4];"
                 : "=r"(r[0]), "=r"(r[1]), "=r"(r[2]), "=r"(r[3]) : "r"(addr));
}
__device__ __forceinline__ void mma16816(float* d, const uint32_t* a, const uint32_t* b) {
    asm volatile(
        "mma.sync.aligned.m16n8k16.row.col.f32.f16.f16.f32 "
        "{%0,%1,%2,%3}, {%4,%5,%6,%7}, {%8,%9}, {%0,%1,%2,%3};"
        : "+f"(d[0]), "+f"(d[1]), "+f"(d[2]), "+f"(d[3])
        : "r"(a[0]), "r"(a[1]), "r"(a[2]), "r"(a[3]), "r"(b[0]), "r"(b[1]));
}
__device__ __forceinline__ uint32_t packh2(float x, float y) {
    __half2 h = __floats2half2_rn(x, y);
    return *reinterpret_cast<uint32_t*>(&h);
}
__device__ __forceinline__ float ex2(float x) {
    float r;
    asm("ex2.approx.ftz.f32 %0, %1;" : "=f"(r) : "f"(x));
    return r;
}
#define CP16(dst, src) asm volatile("cp.async.cg.shared.global [%0], [%1], 16;" :: "r"(dst), "l"(src))
#define CP_COMMIT()    asm volatile("cp.async.commit_group;" ::: "memory")
#define CP_WAIT(n)     asm volatile("cp.async.wait_group %0;" :: "n"(n) : "memory")

// ---------------------------------------------------------------------------
// fp32 -> fp16 conversion
// ---------------------------------------------------------------------------
#define XF4   ((size_t)BATCH * SEQ * EMBED / 4)
#define WQF4  ((size_t)EMBED * 3 * EMBED / 4)
#define WOF4  ((size_t)EMBED * EMBED / 4)
#define TOTF4 (XF4 + WQF4 + WOF4)

__global__ __launch_bounds__(256)
void convert_kernel(const float* __restrict__ x, const float* __restrict__ wq,
                    const float* __restrict__ wo)
{
    size_t i = (size_t)blockIdx.x * 256 + threadIdx.x;
    if (i >= TOTF4) return;
    const float* src;
    __half* dst;
    size_t off;
    if (i < XF4)                { src = x;  dst = g_xh;   off = i; }
    else if (i < XF4 + WQF4)    { src = wq; dst = g_wq_h; off = i - XF4; }
    else                        { src = wo; dst = g_wo_h; off = i - XF4 - WQF4; }
    float4 v = *(const float4*)(src + off * 4);
    uint2 w = {packh2(v.x, v.y), packh2(v.z, v.w)};
    *(uint2*)(dst + off * 4) = w;
}

// ---------------------------------------------------------------------------
// fp16 HMMA GEMM, cp.async 3-stage.  CTA 128x128, BK=32, 128 threads
// (4 warps, 2m x 2n), warp tile 64x64 -> 8 ldmatrix per 32 MMAs.
// ---------------------------------------------------------------------------
#define BM 128
#define BN 128
#define BK 32
#define STAGES 3
#define AST 40
#define BST 136
#define A_STAGE (BM * AST)
#define B_STAGE (BK * BST)
#define GEMM_SMEM ((STAGES * A_STAGE + STAGES * B_STAGE) * 2)  // 56832 B

template <int MODE>
__global__ __launch_bounds__(128)
void hgemm(const __half* __restrict__ A, const __half* __restrict__ B,
           const float* __restrict__ bias, float* __restrict__ C,
           int M, int N, int K)
{
    extern __shared__ __half sm[];
    __half* As = sm;
    __half* Bs = sm + STAGES * A_STAGE;

    const int tid = threadIdx.x;
    const int lane = tid & 31;
    const int wid = tid >> 5;
    const int wy = wid >> 1;   // 0..1
    const int wx = wid & 1;    // 0..1
    const int row0 = blockIdx.y * BM;
    const int col0 = blockIdx.x * BN;

    float acc[4][8][4];
#pragma unroll
    for (int i = 0; i < 4; ++i)
#pragma unroll
        for (int j = 0; j < 8; ++j)
#pragma unroll
            for (int v = 0; v < 4; ++v) acc[i][j][v] = 0.f;

    const int nch = K / BK;

    auto load = [&](int c, int st) {
        __half* as = As + st * A_STAGE;
        __half* bs = Bs + st * B_STAGE;
#pragma unroll
        for (int it = 0; it < 4; ++it) {
            const int idx = tid + it * 128;
            const int r = idx >> 2, c8 = (idx & 3) * 8;
            CP16(smem_u32(as + r * AST + c8),
                 A + (size_t)(row0 + r) * K + c * BK + c8);
        }
#pragma unroll
        for (int it = 0; it < 4; ++it) {
            const int idx = tid + it * 128;
            const int r = idx >> 4, n8 = (idx & 15) * 8;
            CP16(smem_u32(bs + r * BST + n8),
                 B + (size_t)(c * BK + r) * N + col0 + n8);
        }
    };

    load(0, 0); CP_COMMIT();
    load(1, 1); CP_COMMIT();
    CP_WAIT(1);
    __syncthreads();

    for (int c = 0; c < nch; ++c) {
        const int p = c % STAGES;
        const __half* as = As + p * A_STAGE;
        const __half* bs = Bs + p * B_STAGE;

#pragma unroll
        for (int kk = 0; kk < 2; ++kk) {
            uint32_t af[4][4];
#pragma unroll
            for (int i = 0; i < 4; ++i)
                ldm_x4(af[i], smem_u32(as + (wy * 64 + i * 16 + (lane & 15)) * AST
                                          + kk * 16 + (lane >> 4) * 8));
            uint32_t bf[4][4];
#pragma unroll
            for (int q = 0; q < 4; ++q)
                ldm_x4_t(bf[q], smem_u32(bs + (kk * 16 + (lane & 15)) * BST
                                            + wx * 64 + q * 16 + (lane >> 4) * 8));
#pragma unroll
            for (int i = 0; i < 4; ++i)
#pragma unroll
                for (int q = 0; q < 4; ++q) {
                    mma16816(acc[i][2 * q + 0], af[i], &bf[q][0]);
                    mma16816(acc[i][2 * q + 1], af[i], &bf[q][2]);
                }
        }

        if (c + 2 < nch) {
            load(c + 2, (c + 2) % STAGES);
            CP_COMMIT();
            CP_WAIT(1);
            __syncthreads();
        } else if (c + 1 < nch) {
            CP_WAIT(0);
            __syncthreads();
        }
    }

#pragma unroll
    for (int i = 0; i < 4; ++i) {
        const int ra = row0 + wy * 64 + i * 16 + (lane >> 2);
#pragma unroll
        for (int j = 0; j < 8; ++j) {
            const int n = col0 + wx * 64 + j * 8 + (lane & 3) * 2;
            const float b0 = bias[n], b1 = bias[n + 1];
#pragma unroll
            for (int half = 0; half < 2; ++half) {
                const int m = ra + half * 8;
                float v0 = acc[i][j][2 * half + 0] + b0;
                float v1 = acc[i][j][2 * half + 1] + b1;
                if (MODE == 0) {
                    *(float2*)&C[(size_t)m * N + n] = make_float2(v0, v1);
                } else {
                    const int part = n >> 10;
                    const int e = n & 1023;
                    const int h = e >> 6;
                    const int d = e & 63;
                    const int bb = m >> 11;
                    const int s = m & 2047;
                    if (part == 0) { v0 *= QSCALE; v1 *= QSCALE; }
                    __half2 hv = __floats2half2_rn(v0, v1);
                    *(__half2*)&g_qkv_h[((((size_t)part * BATCH + bb) * HEADS + h) * SEQ + s) * HD + d] = hv;
                }
            }
        }
    }
}

// ---------------------------------------------------------------------------
// FlashAttention-2: q-tile 128 (8 warps x 16 rows), kv-tile 64,
// cp.async double-buffered K/V, per-warp skip of fully-masked tiles.
// Dynamic smem: Qs[128][72] + Ks[2][64][72] + Vs[2][64][72] = 55296 B.
// ---------------------------------------------------------------------------
#define FA_SMEM ((128 * 72 + 2 * 64 * 72 + 2 * 64 * 72) * 2)

__global__ __launch_bounds__(256)
void fattn()
{
    extern __shared__ __half fsm[];
    __half (*Qs)[72] = (__half(*)[72])fsm;                    // [128][72]
    __half (*Ks)[64][72] = (__half(*)[64][72])(fsm + 128 * 72);
    __half (*Vs)[64][72] = (__half(*)[64][72])(fsm + 128 * 72 + 2 * 64 * 72);

    const int qb = blockIdx.x;
    const int h  = blockIdx.y;
    const int b  = blockIdx.z;
    const int tid = threadIdx.x;
    const int lane = tid & 31;
    const int w = tid >> 5;
    const int i0 = qb * 128;

    const __half* Qp = g_qkv_h + (((size_t)0 * BATCH + b) * HEADS + h) * SEQ * HD;
    const __half* Kp = g_qkv_h + (((size_t)1 * BATCH + b) * HEADS + h) * SEQ * HD;
    const __half* Vp = g_qkv_h + (((size_t)2 * BATCH + b) * HEADS + h) * SEQ * HD;

    auto loadKV = [&](int jt, int buf) {
        const int j0 = jt * 64;
#pragma unroll
        for (int it = 0; it < 2; ++it) {
            const int idx = tid + it * 256;
            const int r = idx >> 3, c8 = (idx & 7) * 8;
            CP16(smem_u32(&Ks[buf][r][c8]), Kp + (size_t)(j0 + r) * HD + c8);
            CP16(smem_u32(&Vs[buf][r][c8]), Vp + (size_t)(j0 + r) * HD + c8);
        }
    };

    // Q tile: 128 x 64 halves = 1024 chunks
#pragma unroll
    for (int it = 0; it < 4; ++it) {
        const int idx = tid + it * 256;
        const int r = idx >> 3, c8 = (idx & 7) * 8;
        *(uint4*)&Qs[r][c8] = *(const uint4*)(Qp + (size_t)(i0 + r) * HD + c8);
    }
    loadKV(0, 0); CP_COMMIT();
    __syncthreads();
    uint32_t qf[4][4];
#pragma unroll
    for (int kk = 0; kk < 4; ++kk)
        ldm_x4(qf[kk], smem_u32(&Qs[w * 16 + (lane & 15)][kk * 16 + (lane >> 4) * 8]));

    float o[8][4];
#pragma unroll
    for (int j = 0; j < 8; ++j)
#pragma unroll
        for (int v = 0; v < 4; ++v) o[j][v] = 0.f;
    float m_a = -1e30f, m_b = -1e30f, l_a = 0.f, l_b = 0.f;

    const int rowa = i0 + w * 16 + (lane >> 2);
    const int rowb = rowa + 8;
    const int wlast = i0 + w * 16 + 15;   // last q-row this warp owns
    const int ntiles = 2 * qb + 2;

    for (int jt = 0; jt < ntiles; ++jt) {
        const int j0 = jt * 64;
        const int buf = jt & 1;
        if (jt + 1 < ntiles) {
            loadKV(jt + 1, buf ^ 1);
            CP_COMMIT();
            CP_WAIT(1);
        } else {
            CP_WAIT(0);
        }
        __syncthreads();

        if (j0 <= wlast) {   // tile has at least one unmasked column for this warp
            float s[8][4];
#pragma unroll
            for (int j = 0; j < 8; ++j)
#pragma unroll
                for (int v = 0; v < 4; ++v) s[j][v] = 0.f;
#pragma unroll
            for (int kk = 0; kk < 4; ++kk) {
                uint32_t kf[4][4];
#pragma unroll
                for (int np = 0; np < 4; ++np) {
                    const int r8 = lane & 7, sel = lane >> 3;
                    const int n = np * 16 + (sel >> 1) * 8 + r8;
                    const int k = kk * 16 + (sel & 1) * 8;
                    ldm_x4(kf[np], smem_u32(&Ks[buf][n][k]));
                }
#pragma unroll
                for (int np = 0; np < 4; ++np) {
                    mma16816(s[2 * np + 0], qf[kk], &kf[np][0]);
                    mma16816(s[2 * np + 1], qf[kk], &kf[np][2]);
                }
            }

            if (j0 + 63 > i0 + w * 16) {   // diagonal region for this warp
#pragma unroll
                for (int j = 0; j < 8; ++j) {
                    const int c0 = j0 + j * 8 + (lane & 3) * 2;
                    if (c0 > rowa)     s[j][0] = -1e30f;
                    if (c0 + 1 > rowa) s[j][1] = -1e30f;
                    if (c0 > rowb)     s[j][2] = -1e30f;
                    if (c0 + 1 > rowb) s[j][3] = -1e30f;
                }
            }

            float ma = -1e30f, mb = -1e30f;
#pragma unroll
            for (int j = 0; j < 8; ++j) {
                ma = fmaxf(ma, fmaxf(s[j][0], s[j][1]));
                mb = fmaxf(mb, fmaxf(s[j][2], s[j][3]));
            }
            ma = fmaxf(ma, __shfl_xor_sync(0xffffffff, ma, 1));
            ma = fmaxf(ma, __shfl_xor_sync(0xffffffff, ma, 2));
            mb = fmaxf(mb, __shfl_xor_sync(0xffffffff, mb, 1));
            mb = fmaxf(mb, __shfl_xor_sync(0xffffffff, mb, 2));

            const float mna = fmaxf(m_a, ma), mnb = fmaxf(m_b, mb);
            const float alpha_a = ex2(m_a - mna), alpha_b = ex2(m_b - mnb);
            m_a = mna; m_b = mnb;

            float sa = 0.f, sb = 0.f;
#pragma unroll
            for (int j = 0; j < 8; ++j) {
                s[j][0] = ex2(s[j][0] - mna);
                s[j][1] = ex2(s[j][1] - mna);
                s[j][2] = ex2(s[j][2] - mnb);
                s[j][3] = ex2(s[j][3] - mnb);
                sa += s[j][0] + s[j][1];
                sb += s[j][2] + s[j][3];
            }
            sa += __shfl_xor_sync(0xffffffff, sa, 1);
            sa += __shfl_xor_sync(0xffffffff, sa, 2);
            sb += __shfl_xor_sync(0xffffffff, sb, 1);
            sb += __shfl_xor_sync(0xffffffff, sb, 2);
            l_a = l_a * alpha_a + sa;
            l_b = l_b * alpha_b + sb;

#pragma unroll
            for (int j = 0; j < 8; ++j) {
                o[j][0] *= alpha_a; o[j][1] *= alpha_a;
                o[j][2] *= alpha_b; o[j][3] *= alpha_b;
            }

#pragma unroll
            for (int kk = 0; kk < 4; ++kk) {
                uint32_t pf[4];
                pf[0] = packh2(s[2 * kk][0],     s[2 * kk][1]);
                pf[1] = packh2(s[2 * kk][2],     s[2 * kk][3]);
                pf[2] = packh2(s[2 * kk + 1][0], s[2 * kk + 1][1]);
                pf[3] = packh2(s[2 * kk + 1][2], s[2 * kk + 1][3]);
#pragma unroll
                for (int dp = 0; dp < 4; ++dp) {
                    uint32_t vf[4];
                    ldm_x4_t(vf, smem_u32(&Vs[buf][kk * 16 + (lane & 15)][dp * 16 + (lane >> 4) * 8]));
                    mma16816(o[2 * dp + 0], pf, &vf[0]);
                    mma16816(o[2 * dp + 1], pf, &vf[2]);
                }
            }
        }
        __syncthreads();
    }

    const float inva = 1.f / l_a, invb = 1.f / l_b;
#pragma unroll
    for (int j = 0; j < 8; ++j) {
        const int e = h * HD + j * 8 + (lane & 3) * 2;
        *(__half2*)&g_attn_h[((size_t)b * SEQ + rowa) * EMBED + e] =
            __floats2half2_rn(o[j][0] * inva, o[j][1] * inva);
        *(__half2*)&g_attn_h[((size_t)b * SEQ + rowb) * EMBED + e] =
            __floats2half2_rn(o[j][2] * invb, o[j][3] * invb);
    }
}

// ---------------------------------------------------------------------------
extern "C" void kernel_launch(void* const* d_in, const int* in_sizes, int n_in,
                              void* d_out, int out_size)
{
    const float* x    = (const float*)d_in[0];
    const float* Wqkv = (const float*)d_in[1];
    const float* bqkv = (const float*)d_in[2];
    const float* Wout = (const float*)d_in[3];
    const float* bout = (const float*)d_in[4];
    float* out = (float*)d_out;

    void *xh_p = nullptr, *wq_p = nullptr, *wo_p = nullptr, *attn_p = nullptr;
    cudaGetSymbolAddress(&xh_p, g_xh);
    cudaGetSymbolAddress(&wq_p, g_wq_h);
    cudaGetSymbolAddress(&wo_p, g_wo_h);
    cudaGetSymbolAddress(&attn_p, g_attn_h);

    const int M = BATCH * SEQ;

    cudaFuncSetAttribute(hgemm<0>, cudaFuncAttributeMaxDynamicSharedMemorySize, GEMM_SMEM);
    cudaFuncSetAttribute(hgemm<1>, cudaFuncAttributeMaxDynamicSharedMemorySize, GEMM_SMEM);
    cudaFuncSetAttribute(fattn, cudaFuncAttributeMaxDynamicSharedMemorySize, FA_SMEM);

    convert_kernel<<<(unsigned)((TOTF4 + 255) / 256), 256>>>(x, Wqkv, Wout);

    {
        dim3 grid(3 * EMBED / BN, M / BM);  // (24, 32)
        hgemm<1><<<grid, 128, GEMM_SMEM>>>((const __half*)xh_p, (const __half*)wq_p,
                                           bqkv, nullptr, M, 3 * EMBED, EMBED);
    }

    fattn<<<dim3(SEQ / 128, HEADS, BATCH), 256, FA_SMEM>>>();

    {
        dim3 grid(EMBED / BN, M / BM);  // (8, 32)
        hgemm<0><<<grid, 128, GEMM_SMEM>>>((const __half*)attn_p, (const __half*)wo_p,
                                           bout, out, M, EMBED, EMBED);
    }
}